// round 1
// baseline (speedup 1.0000x reference)
#include <cuda_runtime.h>

// Problem constants
#define NN 256
#define TT 1500
#define CHUNK 30          // 1500 / 30 = 50 exact chunks
#define PAD 31            // smem row stride (odd -> conflict-free)

// Precomputed p[s][t][n] = 0.075 * g_max[s][n] * clip(u_s[n][t],0,1)
// Transposed layout [t][n] so per-step loads are coalesced/broadcast.
__device__ float g_pT[2][TT * NN];

__global__ void prep_kernel(const float* __restrict__ u0,
                            const float* __restrict__ u1,
                            const float* __restrict__ ksyn) {
    int idx = blockIdx.x * blockDim.x + threadIdx.x;
    if (idx >= 2 * NN * TT) return;
    int s = idx / (NN * TT);
    int r = idx - s * (NN * TT);
    int n = r / TT;
    int t = r - n * TT;
    const float* u = s ? u1 : u0;
    float k  = ksyn[s * NN + n];
    float gm = k / (20.0f - 2.0f * k);        // num/(e_syn_delta - num*2), R_OP=1
    float a  = u[n * TT + t];
    a = fminf(fmaxf(a, 0.0f), 1.0f);          // clip(u/R_OP, 0, 1)
    g_pT[s][t * NN + n] = 0.075f * gm * a;    // fold DT*0.75 factor in
}

// Block = 256 threads covering a 16(i) x 16(j) tile of cells.
// Each thread integrates one cell; 30 steps buffered in smem, then flushed
// with coalesced 128B warp stores (out layout is (i,j,t), t contiguous).
__global__ __launch_bounds__(256) void sim_kernel(float* __restrict__ out) {
    __shared__ float buf[256 * PAD];

    const int tid  = threadIdx.x;
    const int tx   = tid & 15;          // j within tile
    const int ty   = tid >> 4;          // i within tile
    const int lane = tid & 31;
    const int wid  = tid >> 5;

    const int i = blockIdx.y * 16 + ty;
    const int j = blockIdx.x * 16 + tx;

    const float* __restrict__ p0 = g_pT[0];
    const float* __restrict__ p1 = g_pT[1];

    // global cell index base of this block's tile
    const int cellBase = (blockIdx.y * 16) * NN + blockIdx.x * 16;

    float v = 0.0f;   // E_REST

    for (int t0 = 0; t0 < TT; t0 += CHUNK) {
        // ---- compute CHUNK steps: v' = v*(0.625 - s) + 20*s ----
        #pragma unroll
        for (int k = 0; k < CHUNK; k++) {
            const int t = t0 + k;
            float s = p0[t * NN + i] + p1[t * NN + j];
            v = fmaf(v, 0.625f - s, 20.0f * s);
            buf[tid * PAD + k] = v;
        }
        __syncthreads();

        // ---- flush: each warp writes 32 cells, 30 consecutive t each ----
        if (lane < CHUNK) {
            #pragma unroll
            for (int c = 0; c < 32; c++) {
                const int cell = wid * 32 + c;                 // block-local cell
                const float val = buf[cell * PAD + lane];
                const int g = cellBase + (cell >> 4) * NN + (cell & 15);
                out[g * TT + t0 + lane] = val;
            }
        }
        __syncthreads();
    }
}

extern "C" void kernel_launch(void* const* d_in, const int* in_sizes, int n_in,
                              void* d_out, int out_size) {
    const float* u0   = (const float*)d_in[0];   // u_pre_0 (N,T)
    const float* u1   = (const float*)d_in[1];   // u_pre_1 (N,T)
    const float* ksyn = (const float*)d_in[2];   // k_syn (2,N)
    float* out = (float*)d_out;                  // (N,N,T) fp32

    const int prep_threads = 256;
    const int prep_total   = 2 * NN * TT;
    prep_kernel<<<(prep_total + prep_threads - 1) / prep_threads, prep_threads>>>(u0, u1, ksyn);

    dim3 grid(NN / 16, NN / 16);   // 16 x 16 blocks
    sim_kernel<<<grid, 256>>>(out);
}